// round 7
// baseline (speedup 1.0000x reference)
#include <cuda_runtime.h>
#include <cuda_fp16.h>
#include <math.h>

#define B_  2
#define T_  1024
#define D_  1024
#define H_  16
#define HD_ 64
#define FF_ 4096
#define L_  6
#define V_  50257
#define M_  (B_*T_)        // 2048 rows
#define VP_ 50304          // V padded to 128

// ---------------- scratch (static device globals; no allocation) -------------
__device__ float  g_h   [M_*D_];
__device__ __half g_ln  [M_*D_];
__device__ float  g_q   [M_*D_];
__device__ float  g_k   [M_*D_];
__device__ float  g_v   [M_*D_];
__device__ __half g_attn[M_*D_];
__device__ __half g_mid [M_*FF_];
// fp16 preconverted TRANSPOSED weights: layout [N][K], K contiguous
__device__ __half g_cwq [L_*D_*D_];
__device__ __half g_cwk [L_*D_*D_];
__device__ __half g_cwv [L_*D_*D_];
__device__ __half g_cwo [L_*D_*D_];
__device__ __half g_cw1 [L_*D_*FF_];
__device__ __half g_cw2 [L_*FF_*D_];
__device__ __half g_cpj [(size_t)VP_*D_];

// ---------------- weight conversion: transpose fp32[K][N] -> fp16[Nout][K] ----
__global__ void conv_transpose_h(const float* __restrict__ src, __half* __restrict__ dst,
                                 int K, int N, int Nout) {
    __shared__ float tile[32][33];
    const size_t sbase = (size_t)blockIdx.z * K * N;
    const size_t dbase = (size_t)blockIdx.z * Nout * K;
    int k0 = blockIdx.x * 32, n0 = blockIdx.y * 32;
    for (int i = threadIdx.y; i < 32; i += 8) {
        int n = n0 + threadIdx.x;
        tile[i][threadIdx.x] = (n < N) ? src[sbase + (size_t)(k0 + i) * N + n] : 0.f;
    }
    __syncthreads();
    for (int i = threadIdx.y; i < 32; i += 8) {
        int n = n0 + i;
        if (n < Nout)
            dst[dbase + (size_t)n * K + k0 + threadIdx.x] = __float2half_rn(tile[threadIdx.x][i]);
    }
}

// ---------------- embedding --------------------------------------------------
__global__ void embed_kernel(const int* __restrict__ x,
                             const float* __restrict__ tok,
                             const float* __restrict__ pos,
                             float* __restrict__ h) {
    int row = blockIdx.x;
    int t   = row % T_;
    int id  = x[row];
    const float* te = tok + (size_t)id * D_;
    const float* pe = pos + (size_t)t  * D_;
    float* o = h + (size_t)row * D_;
    for (int d = threadIdx.x; d < D_; d += blockDim.x)
        o[d] = te[d] + pe[d];
}

// ---------------- layernorm (fp16 output) ------------------------------------
__global__ void ln_kernel(const float* __restrict__ in,
                          const float* __restrict__ w,
                          const float* __restrict__ b,
                          __half* __restrict__ out) {
    int row = blockIdx.x;
    int tid = threadIdx.x;
    const float* xr = in + (size_t)row * D_;
    float s = 0.f, sq = 0.f;
    for (int d = tid; d < D_; d += 256) {
        float v = xr[d];
        s  += v;
        sq += v * v;
    }
    __shared__ float rs[256], rq[256];
    rs[tid] = s; rq[tid] = sq;
    __syncthreads();
    for (int off = 128; off > 0; off >>= 1) {
        if (tid < off) { rs[tid] += rs[tid + off]; rq[tid] += rq[tid + off]; }
        __syncthreads();
    }
    float mu  = rs[0] * (1.f / D_);
    float var = rq[0] * (1.f / D_) - mu * mu;
    float inv = rsqrtf(var + 1e-5f);
    __half* o = out + (size_t)row * D_;
    for (int d = tid; d < D_; d += 256)
        o[d] = __float2half_rn((xr[d] - mu) * inv * w[d] + b[d]);
}

// ---------------- fp16 tensor-core GEMM, 3-stage cp.async ---------------------
// C[M x N] = epilogue(A[M x K] @ Wt[N x K]^T + bias)
// A, Wt fp16 K-contiguous. MODE 0: +bias->f32  MODE 1: relu(+bias)->f16
// MODE 2: +bias+R->f32.  GUARD 1: col<N guard (vocab).
#define CPA16(dst_u32, src_ptr) \
    asm volatile("cp.async.cg.shared.global [%0], [%1], 16;" :: "r"(dst_u32), "l"(src_ptr))

__device__ __forceinline__ unsigned smem_u32(const void* p) {
    return (unsigned)__cvta_generic_to_shared(p);
}

__device__ __forceinline__ void mma16(float c[4], const unsigned a[4], const unsigned b[2]) {
    asm volatile(
        "mma.sync.aligned.m16n8k16.row.col.f32.f16.f16.f32 "
        "{%0,%1,%2,%3}, {%4,%5,%6,%7}, {%8,%9}, {%0,%1,%2,%3};\n"
        : "+f"(c[0]), "+f"(c[1]), "+f"(c[2]), "+f"(c[3])
        : "r"(a[0]), "r"(a[1]), "r"(a[2]), "r"(a[3]), "r"(b[0]), "r"(b[1]));
}

#define SAH 40                          // smem row stride in halves (32 data + 8 pad)

template <int BN_>
__device__ __forceinline__ void issue_stage_h(
    __half* As, __half* Bs, const __half* A, const __half* Wt,
    int K, int bm0, int bn0, int k0, int tid)
{
    // A tile: 128 rows x 32 halves (64B) -> 512 x 16B chunks
    #pragma unroll
    for (int j = 0; j < 2; j++) {
        int f = tid + j * 256;
        int row = f >> 2, c8 = (f & 3) * 8;
        CPA16(smem_u32(As + row * SAH + c8), A + (size_t)(bm0 + row) * K + k0 + c8);
    }
    // B tile: BN_ rows x 32 halves
    #pragma unroll
    for (int j = 0; j < BN_ / 64; j++) {
        int f = tid + j * 256;
        int row = f >> 2, c8 = (f & 3) * 8;
        CPA16(smem_u32(Bs + row * SAH + c8), Wt + (size_t)(bn0 + row) * K + k0 + c8);
    }
    asm volatile("cp.async.commit_group;");
}

template <int MODE, int BN_, int GUARD>
__device__ __forceinline__ void hgemm_body(
    const __half* __restrict__ A, const __half* __restrict__ Wt,
    const float* __restrict__ bias, const float* __restrict__ R,
    void* __restrict__ Cv, int K, int N, int bm0, int bn0)
{
    constexpr int ASZ = 128 * SAH;      // halves per A stage
    constexpr int BSZ = BN_ * SAH;      // halves per B stage
    constexpr int NI  = BN_ / 32;

    extern __shared__ __half smh[];
    __half* As = smh;
    __half* Bs = smh + 3 * ASZ;

    const int tid  = threadIdx.x;
    const int lane = tid & 31;
    const int warp = tid >> 5;
    const int g    = lane >> 2;
    const int tg   = lane & 3;
    const int wm0  = (warp >> 2) * 64;
    const int wn0  = (warp & 3) * (BN_ / 4);

    float acc[4][NI][4];
    #pragma unroll
    for (int mi = 0; mi < 4; mi++)
        #pragma unroll
        for (int ni = 0; ni < NI; ni++)
            #pragma unroll
            for (int r = 0; r < 4; r++) acc[mi][ni][r] = 0.f;

    const int nIter = K / 32;
    issue_stage_h<BN_>(As, Bs, A, Wt, K, bm0, bn0, 0, tid);
    issue_stage_h<BN_>(As + ASZ, Bs + BSZ, A, Wt, K, bm0, bn0, 32, tid);

    int st = 0, stw = 2;
    for (int t = 0; t < nIter; t++) {
        if (t + 1 < nIter) asm volatile("cp.async.wait_group 1;");
        else               asm volatile("cp.async.wait_group 0;");
        __syncthreads();

        const __half* Ast = As + st * ASZ;
        const __half* Bst = Bs + st * BSZ;
        #pragma unroll
        for (int kk = 0; kk < 32; kk += 16) {
            unsigned a[4][4], b[NI][2];
            #pragma unroll
            for (int mi = 0; mi < 4; mi++) {
                int r0 = wm0 + mi * 16 + g;
                a[mi][0] = *(const unsigned*)&Ast[(r0    ) * SAH + kk + 2 * tg];
                a[mi][1] = *(const unsigned*)&Ast[(r0 + 8) * SAH + kk + 2 * tg];
                a[mi][2] = *(const unsigned*)&Ast[(r0    ) * SAH + kk + 2 * tg + 8];
                a[mi][3] = *(const unsigned*)&Ast[(r0 + 8) * SAH + kk + 2 * tg + 8];
            }
            #pragma unroll
            for (int ni = 0; ni < NI; ni++) {
                int c = wn0 + ni * 8 + g;
                b[ni][0] = *(const unsigned*)&Bst[c * SAH + kk + 2 * tg];
                b[ni][1] = *(const unsigned*)&Bst[c * SAH + kk + 2 * tg + 8];
            }
            #pragma unroll
            for (int mi = 0; mi < 4; mi++)
                #pragma unroll
                for (int ni = 0; ni < NI; ni++)
                    mma16(acc[mi][ni], a[mi], b[ni]);
        }

        if (t + 2 < nIter) {
            issue_stage_h<BN_>(As + stw * ASZ, Bs + stw * BSZ, A, Wt, K, bm0, bn0,
                               (t + 2) * 32, tid);
            stw = (stw == 2) ? 0 : stw + 1;
        }
        st = (st == 2) ? 0 : st + 1;
    }

    // epilogue
    #pragma unroll
    for (int mi = 0; mi < 4; mi++) {
        #pragma unroll
        for (int ni = 0; ni < NI; ni++) {
            int row0 = bm0 + wm0 + mi * 16 + g;
            int col0 = bn0 + wn0 + ni * 8 + 2 * tg;
            #pragma unroll
            for (int rr = 0; rr < 2; rr++) {
                int row = row0 + rr * 8;
                if (MODE == 1) {
                    // fp16 output (FFN1 mid), store half2
                    float v0 = fmaxf(acc[mi][ni][rr * 2 + 0] + bias[col0 + 0], 0.f);
                    float v1 = fmaxf(acc[mi][ni][rr * 2 + 1] + bias[col0 + 1], 0.f);
                    *(__half2*)((__half*)Cv + (size_t)row * N + col0) =
                        __floats2half2_rn(v0, v1);
                } else {
                    float* C = (float*)Cv;
                    #pragma unroll
                    for (int cc = 0; cc < 2; cc++) {
                        int col = col0 + cc;
                        if (!GUARD || col < N) {
                            float v = acc[mi][ni][rr * 2 + cc] + bias[col];
                            if (MODE == 2) v += R[(size_t)row * N + col];
                            C[(size_t)row * N + col] = v;
                        }
                    }
                }
            }
        }
    }
}

template <int MODE, int BN_, int GUARD>
__global__ __launch_bounds__(256, 2)
void hgemm(const __half* __restrict__ A, const __half* __restrict__ Wt,
           const float* __restrict__ bias, const float* __restrict__ R,
           void* __restrict__ C, int K, int N) {
    hgemm_body<MODE, BN_, GUARD>(A, Wt, bias, R, C, K, N,
                                 blockIdx.y * 128, blockIdx.x * BN_);
}

__global__ __launch_bounds__(256, 2)
void hgemm_qkv(const __half* __restrict__ A,
               const __half* __restrict__ wq, const __half* __restrict__ wk,
               const __half* __restrict__ wv,
               const float* __restrict__ bq, const float* __restrict__ bk,
               const float* __restrict__ bv,
               float* __restrict__ q, float* __restrict__ k, float* __restrict__ v) {
    int z = blockIdx.z;
    const __half* W   = (z == 0) ? wq : (z == 1) ? wk : wv;
    const float* bias = (z == 0) ? bq : (z == 1) ? bk : bv;
    float*       C    = (z == 0) ? q  : (z == 1) ? k  : v;
    hgemm_body<0, 128, 0>(A, W, bias, nullptr, C, D_, D_,
                          blockIdx.y * 128, blockIdx.x * 128);
}

// ---------------- flash attention (fp32 math, fp16 output) --------------------
#define QT 64
#define KT 32

__global__ __launch_bounds__(256)
void flash_attn(const float* __restrict__ q,
                const float* __restrict__ k,
                const float* __restrict__ v,
                __half* __restrict__ out) {
    const int q0  = blockIdx.x * QT;
    const int h   = blockIdx.y;
    const int b   = blockIdx.z;
    const int tid = threadIdx.x;
    const int qr  = tid >> 2;
    const int qt  = tid & 3;

    __shared__ float Qs[QT][68];
    __shared__ float Ks[KT][68];
    __shared__ float Vs[KT][68];
    __shared__ float Ps[QT][33];

    const size_t base = ((size_t)b * T_) * D_ + (size_t)h * HD_;
    const int qg = q0 + qr;

    #pragma unroll
    for (int i = tid; i < QT * 16; i += 256) {
        int r = i >> 4, c4 = (i & 15) << 2;
        *(float4*)&Qs[r][c4] = *(const float4*)&q[base + (size_t)(q0 + r) * D_ + c4];
    }

    float o[16];
    #pragma unroll
    for (int i = 0; i < 16; i++) o[i] = 0.f;
    float m = -1e30f, l = 0.f;

    const int nTiles = (q0 + QT) / KT;
    __syncthreads();

    for (int t0 = 0; t0 < nTiles; t0++) {
        const int s0 = t0 * KT;
        #pragma unroll
        for (int i = tid; i < KT * 16; i += 256) {
            int r = i >> 4, c4 = (i & 15) << 2;
            *(float4*)&Ks[r][c4] = *(const float4*)&k[base + (size_t)(s0 + r) * D_ + c4];
            *(float4*)&Vs[r][c4] = *(const float4*)&v[base + (size_t)(s0 + r) * D_ + c4];
        }
        __syncthreads();

        float s[8];
        #pragma unroll
        for (int j = 0; j < 8; j++) s[j] = 0.f;
        #pragma unroll
        for (int d4 = 0; d4 < 16; d4++) {
            float4 qv = *(const float4*)&Qs[qr][d4 << 2];
            #pragma unroll
            for (int j = 0; j < 8; j++) {
                float4 kv4 = *(const float4*)&Ks[qt * 8 + j][d4 << 2];
                s[j] += qv.x * kv4.x + qv.y * kv4.y + qv.z * kv4.z + qv.w * kv4.w;
            }
        }
        #pragma unroll
        for (int j = 0; j < 8; j++) {
            int kvg = s0 + qt * 8 + j;
            s[j] = (kvg <= qg) ? s[j] * 0.125f : -1e30f;
        }
        float tm = s[0];
        #pragma unroll
        for (int j = 1; j < 8; j++) tm = fmaxf(tm, s[j]);
        tm = fmaxf(tm, __shfl_xor_sync(0xffffffffu, tm, 1));
        tm = fmaxf(tm, __shfl_xor_sync(0xffffffffu, tm, 2));
        float m_new = fmaxf(m, tm);
        float scale = __expf(m - m_new);
        float ps = 0.f;
        #pragma unroll
        for (int j = 0; j < 8; j++) { s[j] = __expf(s[j] - m_new); ps += s[j]; }
        ps += __shfl_xor_sync(0xffffffffu, ps, 1);
        ps += __shfl_xor_sync(0xffffffffu, ps, 2);
        l = l * scale + ps;
        m = m_new;
        #pragma unroll
        for (int i = 0; i < 16; i++) o[i] *= scale;
        #pragma unroll
        for (int j = 0; j < 8; j++) Ps[qr][qt * 8 + j] = s[j];
        __syncthreads();

        #pragma unroll 4
        for (int kv = 0; kv < KT; kv++) {
            float p = Ps[qr][kv];
            #pragma unroll
            for (int d4 = 0; d4 < 4; d4++) {
                float4 vv = *(const float4*)&Vs[kv][qt * 16 + (d4 << 2)];
                o[d4 * 4 + 0] += p * vv.x;
                o[d4 * 4 + 1] += p * vv.y;
                o[d4 * 4 + 2] += p * vv.z;
                o[d4 * 4 + 3] += p * vv.w;
            }
        }
        __syncthreads();
    }

    float inv = 1.f / l;
    __half* op = out + base + (size_t)qg * D_ + qt * 16;
    #pragma unroll
    for (int d4 = 0; d4 < 4; d4++) {
        *(__half2*)(op + d4 * 4 + 0) = __floats2half2_rn(o[d4*4+0]*inv, o[d4*4+1]*inv);
        *(__half2*)(op + d4 * 4 + 2) = __floats2half2_rn(o[d4*4+2]*inv, o[d4*4+3]*inv);
    }
}

// ---------------- launch -----------------------------------------------------
extern "C" void kernel_launch(void* const* d_in, const int* in_sizes, int n_in,
                              void* d_out, int out_size) {
    const int*   x       = (const int*)  d_in[0];
    const float* tok_emb = (const float*)d_in[1];
    const float* pos_emb = (const float*)d_in[2];
    const float* wq      = (const float*)d_in[3];
    const float* bq      = (const float*)d_in[4];
    const float* wk      = (const float*)d_in[5];
    const float* bk      = (const float*)d_in[6];
    const float* wv      = (const float*)d_in[7];
    const float* bv      = (const float*)d_in[8];
    const float* wo      = (const float*)d_in[9];
    const float* bo      = (const float*)d_in[10];
    const float* ln1_w   = (const float*)d_in[11];
    const float* ln1_b   = (const float*)d_in[12];
    const float* ln2_w   = (const float*)d_in[13];
    const float* ln2_b   = (const float*)d_in[14];
    const float* ffn_w1  = (const float*)d_in[15];
    const float* ffn_b1  = (const float*)d_in[16];
    const float* ffn_w2  = (const float*)d_in[17];
    const float* ffn_b2  = (const float*)d_in[18];
    const float* lnf_w   = (const float*)d_in[19];
    const float* lnf_b   = (const float*)d_in[20];
    const float* proj_w  = (const float*)d_in[21];
    const float* proj_b  = (const float*)d_in[22];
    float* logits = (float*)d_out;

    float  *h, *q, *k, *v;
    __half *ln, *attn, *mid;
    __half *cwq, *cwk, *cwv, *cwo, *cw1, *cw2, *cpj;
    cudaGetSymbolAddress((void**)&h,    g_h);
    cudaGetSymbolAddress((void**)&ln,   g_ln);
    cudaGetSymbolAddress((void**)&q,    g_q);
    cudaGetSymbolAddress((void**)&k,    g_k);
    cudaGetSymbolAddress((void**)&v,    g_v);
    cudaGetSymbolAddress((void**)&attn, g_attn);
    cudaGetSymbolAddress((void**)&mid,  g_mid);
    cudaGetSymbolAddress((void**)&cwq,  g_cwq);
    cudaGetSymbolAddress((void**)&cwk,  g_cwk);
    cudaGetSymbolAddress((void**)&cwv,  g_cwv);
    cudaGetSymbolAddress((void**)&cwo,  g_cwo);
    cudaGetSymbolAddress((void**)&cw1,  g_cw1);
    cudaGetSymbolAddress((void**)&cw2,  g_cw2);
    cudaGetSymbolAddress((void**)&cpj,  g_cpj);

    const int SMEM128 = 3 * (128 * SAH + 128 * SAH) * 2;   // 61440 B
    const int SMEM64  = 3 * (128 * SAH + 64  * SAH) * 2;   // 46080 B
    cudaFuncSetAttribute(hgemm<2,64,0>,  cudaFuncAttributeMaxDynamicSharedMemorySize, SMEM64);
    cudaFuncSetAttribute(hgemm<1,128,0>, cudaFuncAttributeMaxDynamicSharedMemorySize, SMEM128);
    cudaFuncSetAttribute(hgemm<0,128,1>, cudaFuncAttributeMaxDynamicSharedMemorySize, SMEM128);
    cudaFuncSetAttribute(hgemm_qkv,      cudaFuncAttributeMaxDynamicSharedMemorySize, SMEM128);

    // ---- weight conversion: transpose + fp16 round, once per call ----
    dim3 ctb(32, 8);
    conv_transpose_h<<<dim3(D_/32,  D_/32,  L_), ctb>>>(wq,     cwq, D_,  D_,  D_);
    conv_transpose_h<<<dim3(D_/32,  D_/32,  L_), ctb>>>(wk,     cwk, D_,  D_,  D_);
    conv_transpose_h<<<dim3(D_/32,  D_/32,  L_), ctb>>>(wv,     cwv, D_,  D_,  D_);
    conv_transpose_h<<<dim3(D_/32,  D_/32,  L_), ctb>>>(wo,     cwo, D_,  D_,  D_);
    conv_transpose_h<<<dim3(D_/32,  FF_/32, L_), ctb>>>(ffn_w1, cw1, D_,  FF_, FF_);
    conv_transpose_h<<<dim3(FF_/32, D_/32,  L_), ctb>>>(ffn_w2, cw2, FF_, D_,  D_);
    conv_transpose_h<<<dim3(D_/32,  VP_/32, 1 ), ctb>>>(proj_w, cpj, D_,  V_,  VP_);

    embed_kernel<<<M_, 256>>>(x, tok_emb, pos_emb, h);

    dim3 gDD64(D_ / 64, M_ / 128);           // (16,16)
    dim3 gQKV(D_ / 128, M_ / 128, 3);        // (8,16,3)
    dim3 gFF1(FF_ / 128, M_ / 128);          // (32,16)
    dim3 gPRJ(VP_ / 128, M_ / 128);          // (393,16)
    dim3 gAT(T_ / QT, H_, B_);

    for (int l = 0; l < L_; l++) {
        __half* cwq_l = cwq + (size_t)l * D_ * D_;
        __half* cwk_l = cwk + (size_t)l * D_ * D_;
        __half* cwv_l = cwv + (size_t)l * D_ * D_;
        __half* cwo_l = cwo + (size_t)l * D_ * D_;
        __half* cw1_l = cw1 + (size_t)l * D_ * FF_;
        __half* cw2_l = cw2 + (size_t)l * FF_ * D_;

        ln_kernel<<<M_, 256>>>(h, ln1_w + l * D_, ln1_b + l * D_, ln);

        hgemm_qkv<<<gQKV, 256, SMEM128>>>(ln, cwq_l, cwk_l, cwv_l,
                                          bq + l * D_, bk + l * D_, bv + l * D_, q, k, v);

        flash_attn<<<gAT, 256>>>(q, k, v, attn);

        hgemm<2,64,0><<<gDD64, 256, SMEM64>>>(attn, cwo_l, bo + l * D_, h, h, D_, D_);

        ln_kernel<<<M_, 256>>>(h, ln2_w + l * D_, ln2_b + l * D_, ln);

        hgemm<1,128,0><<<gFF1, 256, SMEM128>>>(ln, cw1_l, ffn_b1 + l * FF_, nullptr,
                                               mid, D_, FF_);
        hgemm<2,64,0><<<gDD64, 256, SMEM64>>>(mid, cw2_l, ffn_b2 + l * D_, h, h, FF_, D_);
    }

    ln_kernel<<<M_, 256>>>(h, lnf_w, lnf_b, ln);
    hgemm<0,128,1><<<gPRJ, 256, SMEM128>>>(ln, cpj, proj_b, nullptr, logits, D_, V_);
}

// round 8
// speedup vs baseline: 1.2675x; 1.2675x over previous
#include <cuda_runtime.h>
#include <math.h>

#define B_  2
#define T_  1024
#define D_  1024
#define H_  16
#define HD_ 64
#define FF_ 4096
#define L_  6
#define V_  50257
#define M_  (B_*T_)        // 2048 rows
#define VP_ 50304          // V padded to 192*262 (also /128)

// ---------------- scratch (static device globals; no allocation) -------------
__device__ float g_h   [M_*D_];
__device__ float g_ln  [M_*D_];
__device__ float g_q   [M_*D_];
__device__ float g_k   [M_*D_];
__device__ float g_v   [M_*D_];
__device__ float g_attn[M_*D_];
__device__ float g_mid [M_*FF_];
// tf32-preconverted weights (row-major [K][N])
__device__ float g_cwq [L_*D_*D_];
__device__ float g_cwk [L_*D_*D_];
__device__ float g_cwv [L_*D_*D_];
__device__ float g_cwo [L_*D_*D_];
__device__ float g_cw1 [L_*D_*FF_];
__device__ float g_cw2 [L_*FF_*D_];
__device__ float g_cpj [(size_t)D_*VP_];

__device__ __forceinline__ float f2tf(float x) {
    unsigned u;
    asm("cvt.rna.tf32.f32 %0, %1;" : "=r"(u) : "f"(x));
    return __uint_as_float(u);
}

// ---------------- weight conversion ------------------------------------------
__global__ void conv_tf32(const float4* __restrict__ src, float4* __restrict__ dst, int n4) {
    for (int i = blockIdx.x * blockDim.x + threadIdx.x; i < n4; i += gridDim.x * blockDim.x) {
        float4 v = src[i];
        dst[i] = make_float4(f2tf(v.x), f2tf(v.y), f2tf(v.z), f2tf(v.w));
    }
}

__global__ void conv_proj(const float* __restrict__ src, float* __restrict__ dst) {
    const long long total = (long long)D_ * VP_;
    for (long long i = (long long)blockIdx.x * blockDim.x + threadIdx.x; i < total;
         i += (long long)gridDim.x * blockDim.x) {
        int row = (int)(i / VP_), col = (int)(i - (long long)row * VP_);
        dst[i] = (col < V_) ? f2tf(src[(size_t)row * V_ + col]) : 0.f;
    }
}

// ---------------- embedding --------------------------------------------------
__global__ void embed_kernel(const int* __restrict__ x,
                             const float* __restrict__ tok,
                             const float* __restrict__ pos,
                             float* __restrict__ h) {
    int row = blockIdx.x;
    int t   = row % T_;
    int id  = x[row];
    const float* te = tok + (size_t)id * D_;
    const float* pe = pos + (size_t)t  * D_;
    float* o = h + (size_t)row * D_;
    for (int d = threadIdx.x; d < D_; d += blockDim.x)
        o[d] = te[d] + pe[d];
}

// ---------------- layernorm (tf32-rounded output) ----------------------------
__global__ void ln_kernel(const float* __restrict__ in,
                          const float* __restrict__ w,
                          const float* __restrict__ b,
                          float* __restrict__ out) {
    int row = blockIdx.x;
    int tid = threadIdx.x;
    const float* xr = in + (size_t)row * D_;
    float s = 0.f, sq = 0.f;
    for (int d = tid; d < D_; d += 256) {
        float v = xr[d];
        s  += v;
        sq += v * v;
    }
    __shared__ float rs[256], rq[256];
    rs[tid] = s; rq[tid] = sq;
    __syncthreads();
    for (int off = 128; off > 0; off >>= 1) {
        if (tid < off) { rs[tid] += rs[tid + off]; rq[tid] += rq[tid + off]; }
        __syncthreads();
    }
    float mu  = rs[0] * (1.f / D_);
    float var = rq[0] * (1.f / D_) - mu * mu;
    float inv = rsqrtf(var + 1e-5f);
    float* o = out + (size_t)row * D_;
    for (int d = tid; d < D_; d += 256)
        o[d] = f2tf((xr[d] - mu) * inv * w[d] + b[d]);
}

// ---------------- common GEMM helpers ------------------------------------------
#define CPA16(dst_u32, src_ptr) \
    asm volatile("cp.async.cg.shared.global [%0], [%1], 16;" :: "r"(dst_u32), "l"(src_ptr))

__device__ __forceinline__ unsigned smem_u32(const void* p) {
    return (unsigned)__cvta_generic_to_shared(p);
}

__device__ __forceinline__ void mma8(float c[4], const unsigned a[4], const unsigned b[2]) {
    asm volatile(
        "mma.sync.aligned.m16n8k8.row.col.f32.tf32.tf32.f32 "
        "{%0,%1,%2,%3}, {%4,%5,%6,%7}, {%8,%9}, {%0,%1,%2,%3};\n"
        : "+f"(c[0]), "+f"(c[1]), "+f"(c[2]), "+f"(c[3])
        : "r"(a[0]), "r"(a[1]), "r"(a[2]), "r"(a[3]), "r"(b[0]), "r"(b[1]));
}

// ---------------- standard GEMM: 128 x BN_, 3-stage cp.async (R4 proven) ------
template <int BN_>
__device__ __forceinline__ void issue_stage(
    float* As, float* Bs, const float* A, const float* W,
    int K, int Npad, int bm0, int bn0, int k0, int tid)
{
    constexpr int SB = BN_ + 8;
    #pragma unroll
    for (int j = 0; j < 4; j++) {
        int f = tid + j * 256;
        int row = f >> 3, c4 = (f & 7) << 2;
        CPA16(smem_u32(As + row * 36 + c4), A + (size_t)(bm0 + row) * K + k0 + c4);
    }
    #pragma unroll
    for (int j = 0; j < BN_ / 32; j++) {
        int f = tid + j * 256;
        int row = (BN_ == 128) ? (f >> 5) : (f >> 4);
        int c4  = (BN_ == 128) ? ((f & 31) << 2) : ((f & 15) << 2);
        CPA16(smem_u32(Bs + row * SB + c4), W + (size_t)(k0 + row) * Npad + bn0 + c4);
    }
    asm volatile("cp.async.commit_group;");
}

template <int MODE, int BN_>
__device__ __forceinline__ void tgemm_body(
    const float* __restrict__ A, const float* __restrict__ W,
    const float* __restrict__ bias, const float* __restrict__ R,
    float* __restrict__ C, int K, int N, int Npad, int bm0, int bn0)
{
    constexpr int SB  = BN_ + 8;
    constexpr int ASZ = 128 * 36;
    constexpr int BSZ = 32 * SB;
    constexpr int NI  = BN_ / 32;

    extern __shared__ float sm[];
    float* As = sm;
    float* Bs = sm + 3 * ASZ;

    const int tid  = threadIdx.x;
    const int lane = tid & 31;
    const int warp = tid >> 5;
    const int g    = lane >> 2;
    const int tg   = lane & 3;
    const int wm0  = (warp >> 2) * 64;
    const int wn0  = (warp & 3) * (BN_ / 4);

    float acc[4][NI][4];
    #pragma unroll
    for (int mi = 0; mi < 4; mi++)
        #pragma unroll
        for (int ni = 0; ni < NI; ni++)
            #pragma unroll
            for (int r = 0; r < 4; r++) acc[mi][ni][r] = 0.f;

    const int nIter = K / 32;
    issue_stage<BN_>(As, Bs, A, W, K, Npad, bm0, bn0, 0, tid);
    issue_stage<BN_>(As + ASZ, Bs + BSZ, A, W, K, Npad, bm0, bn0, 32, tid);

    int st = 0, stw = 2;
    for (int t = 0; t < nIter; t++) {
        if (t + 1 < nIter) asm volatile("cp.async.wait_group 1;");
        else               asm volatile("cp.async.wait_group 0;");
        __syncthreads();

        const float* Ast = As + st * ASZ;
        const float* Bst = Bs + st * BSZ;
        #pragma unroll
        for (int kk = 0; kk < 32; kk += 8) {
            unsigned a[4][4], b[NI][2];
            #pragma unroll
            for (int mi = 0; mi < 4; mi++) {
                int r0 = wm0 + mi * 16 + g;
                a[mi][0] = __float_as_uint(Ast[(r0    ) * 36 + kk + tg]);
                a[mi][1] = __float_as_uint(Ast[(r0 + 8) * 36 + kk + tg]);
                a[mi][2] = __float_as_uint(Ast[(r0    ) * 36 + kk + tg + 4]);
                a[mi][3] = __float_as_uint(Ast[(r0 + 8) * 36 + kk + tg + 4]);
            }
            #pragma unroll
            for (int ni = 0; ni < NI; ni++) {
                int c = wn0 + ni * 8 + g;
                b[ni][0] = __float_as_uint(Bst[(kk + tg    ) * SB + c]);
                b[ni][1] = __float_as_uint(Bst[(kk + tg + 4) * SB + c]);
            }
            #pragma unroll
            for (int mi = 0; mi < 4; mi++)
                #pragma unroll
                for (int ni = 0; ni < NI; ni++)
                    mma8(acc[mi][ni], a[mi], b[ni]);
        }

        if (t + 2 < nIter) {
            issue_stage<BN_>(As + stw * ASZ, Bs + stw * BSZ, A, W, K, Npad, bm0, bn0,
                             (t + 2) * 32, tid);
            stw = (stw == 2) ? 0 : stw + 1;
        }
        st = (st == 2) ? 0 : st + 1;
    }

    #pragma unroll
    for (int mi = 0; mi < 4; mi++) {
        #pragma unroll
        for (int ni = 0; ni < NI; ni++) {
            int row0 = bm0 + wm0 + mi * 16 + g;
            int col0 = bn0 + wn0 + ni * 8 + 2 * tg;
            #pragma unroll
            for (int rr = 0; rr < 2; rr++) {
                int row = row0 + rr * 8;
                #pragma unroll
                for (int cc = 0; cc < 2; cc++) {
                    int col = col0 + cc;
                    float v = acc[mi][ni][rr * 2 + cc] + bias[col];
                    if (MODE == 1) v = f2tf(fmaxf(v, 0.f));
                    if (MODE == 2) v += R[(size_t)row * N + col];
                    C[(size_t)row * N + col] = v;
                }
            }
        }
    }
}

template <int MODE, int BN_>
__global__ __launch_bounds__(256, 2)
void tgemm(const float* __restrict__ A, const float* __restrict__ W,
           const float* __restrict__ bias, const float* __restrict__ R,
           float* __restrict__ C, int K, int N, int Npad) {
    tgemm_body<MODE, BN_>(A, W, bias, R, C, K, N, Npad,
                          blockIdx.y * 128, blockIdx.x * BN_);
}

__global__ __launch_bounds__(256, 2)
void tgemm_qkv(const float* __restrict__ A,
               const float* __restrict__ wq, const float* __restrict__ wk,
               const float* __restrict__ wv,
               const float* __restrict__ bq, const float* __restrict__ bk,
               const float* __restrict__ bv,
               float* __restrict__ q, float* __restrict__ k, float* __restrict__ v) {
    int z = blockIdx.z;
    const float* W    = (z == 0) ? wq : (z == 1) ? wk : wv;
    const float* bias = (z == 0) ? bq : (z == 1) ? bk : bv;
    float*       C    = (z == 0) ? q  : (z == 1) ? k  : v;
    tgemm_body<0, 128>(A, W, bias, nullptr, C, D_, D_, D_,
                       blockIdx.y * 128, blockIdx.x * 128);
}

// ---------------- HYBRID GEMM: 128x192 tile, MMA(128 cols) + FFMA(64 cols) ----
// 384 threads: warps 0-7 tensor-core path, warps 8-11 fp32 FFMA path.
// Used for the vocab projection (N=50257, Npad=50304=192*262). GUARDed stores.
#define HSA 36
#define HSB 136
#define HSF 72
#define HASZ (128*HSA)
#define HBSZ (32*HSB)
#define HFSZ (32*HSF)
#define SMEM_HYB (3*(HASZ+HBSZ+HFSZ)*4)   // 135168 B

__device__ __forceinline__ void issue_hyb(
    float* As, float* Bt, float* Bf,
    const float* A, const float* W,
    int K, int Npad, int bm0, int bn0, int k0, int tid)
{
    if (tid < 256) {
        #pragma unroll
        for (int j = 0; j < 4; j++) {
            int f = tid + j * 256;
            int row = f >> 3, c4 = (f & 7) << 2;
            CPA16(smem_u32(As + row * HSA + c4), A + (size_t)(bm0 + row) * K + k0 + c4);
        }
        #pragma unroll
        for (int j = 0; j < 4; j++) {
            int f = tid + j * 256;
            int row = f >> 5, c4 = (f & 31) << 2;
            CPA16(smem_u32(Bt + row * HSB + c4), W + (size_t)(k0 + row) * Npad + bn0 + c4);
        }
    } else {
        int tt = tid - 256;
        #pragma unroll
        for (int j = 0; j < 4; j++) {
            int f = tt + j * 128;
            int row = f >> 4, c4 = (f & 15) << 2;
            CPA16(smem_u32(Bf + row * HSF + c4),
                  W + (size_t)(k0 + row) * Npad + bn0 + 128 + c4);
        }
    }
    asm volatile("cp.async.commit_group;");
}

__global__ __launch_bounds__(384, 1)
void tgemm_hyb(const float* __restrict__ A, const float* __restrict__ W,
               const float* __restrict__ bias, float* __restrict__ C,
               int K, int N, int Npad) {
    extern __shared__ float sm[];
    float* As = sm;                        // [3][128][36]
    float* Bt = sm + 3 * HASZ;             // [3][32][136]
    float* Bf = sm + 3 * (HASZ + HBSZ);    // [3][32][72]

    const int tid  = threadIdx.x;
    const int lane = tid & 31;
    const int warp = tid >> 5;
    const int bm0  = blockIdx.y * 128;
    const int bn0  = blockIdx.x * 192;
    const int nIter = K / 32;

    issue_hyb(As, Bt, Bf, A, W, K, Npad, bm0, bn0, 0, tid);
    issue_hyb(As + HASZ, Bt + HBSZ, Bf + HFSZ, A, W, K, Npad, bm0, bn0, 32, tid);

    if (warp < 8) {
        // ---- tensor-core path: 128x128 sub-tile ----
        const int g   = lane >> 2;
        const int tg  = lane & 3;
        const int wm0 = (warp >> 2) * 64;
        const int wn0 = (warp & 3) * 32;

        float acc[4][4][4];
        #pragma unroll
        for (int mi = 0; mi < 4; mi++)
            #pragma unroll
            for (int ni = 0; ni < 4; ni++)
                #pragma unroll
                for (int r = 0; r < 4; r++) acc[mi][ni][r] = 0.f;

        int st = 0, stw = 2;
        for (int t = 0; t < nIter; t++) {
            if (t + 1 < nIter) asm volatile("cp.async.wait_group 1;");
            else               asm volatile("cp.async.wait_group 0;");
            __syncthreads();

            const float* Ast = As + st * HASZ;
            const float* Bst = Bt + st * HBSZ;
            #pragma unroll
            for (int kk = 0; kk < 32; kk += 8) {
                unsigned a[4][4], b[4][2];
                #pragma unroll
                for (int mi = 0; mi < 4; mi++) {
                    int r0 = wm0 + mi * 16 + g;
                    a[mi][0] = __float_as_uint(Ast[(r0    ) * HSA + kk + tg]);
                    a[mi][1] = __float_as_uint(Ast[(r0 + 8) * HSA + kk + tg]);
                    a[mi][2] = __float_as_uint(Ast[(r0    ) * HSA + kk + tg + 4]);
                    a[mi][3] = __float_as_uint(Ast[(r0 + 8) * HSA + kk + tg + 4]);
                }
                #pragma unroll
                for (int ni = 0; ni < 4; ni++) {
                    int c = wn0 + ni * 8 + g;
                    b[ni][0] = __float_as_uint(Bst[(kk + tg    ) * HSB + c]);
                    b[ni][1] = __float_as_uint(Bst[(kk + tg + 4) * HSB + c]);
                }
                #pragma unroll
                for (int mi = 0; mi < 4; mi++)
                    #pragma unroll
                    for (int ni = 0; ni < 4; ni++)
                        mma8(acc[mi][ni], a[mi], b[ni]);
            }

            if (t + 2 < nIter) {
                issue_hyb(As + stw * HASZ, Bt + stw * HBSZ, Bf + stw * HFSZ,
                          A, W, K, Npad, bm0, bn0, (t + 2) * 32, tid);
                stw = (stw == 2) ? 0 : stw + 1;
            }
            st = (st == 2) ? 0 : st + 1;
        }

        #pragma unroll
        for (int mi = 0; mi < 4; mi++) {
            #pragma unroll
            for (int ni = 0; ni < 4; ni++) {
                int row0 = bm0 + wm0 + mi * 16 + g;
                int col0 = bn0 + wn0 + ni * 8 + 2 * tg;
                #pragma unroll
                for (int rr = 0; rr < 2; rr++) {
                    int row = row0 + rr * 8;
                    #pragma unroll
                    for (int cc = 0; cc < 2; cc++) {
                        int col = col0 + cc;
                        if (col < N)
                            C[(size_t)row * N + col] = acc[mi][ni][rr * 2 + cc] + bias[col];
                    }
                }
            }
        }
    } else {
        // ---- FFMA path: 128x64 sub-tile (cols bn0+128 .. bn0+191) ----
        const int wf = warp - 8;            // 0..3
        const int ly = lane >> 3;           // 0..3
        const int lx = lane & 7;            // 0..7
        const int rb = wf * 32 + ly * 8;    // local row base
        const int cb = lx * 8;              // local col base in fma slab

        float facc[8][8];
        #pragma unroll
        for (int i = 0; i < 8; i++)
            #pragma unroll
            for (int j = 0; j < 8; j++) facc[i][j] = 0.f;

        int st = 0, stw = 2;
        for (int t = 0; t < nIter; t++) {
            if (t + 1 < nIter) asm volatile("cp.async.wait_group 1;");
            else               asm volatile("cp.async.wait_group 0;");
            __syncthreads();

            const float* Ast = As + st * HASZ;
            const float* Bft = Bf + st * HFSZ;
            #pragma unroll 8
            for (int kk = 0; kk < 32; kk++) {
                float a[8];
                #pragma unroll
                for (int i = 0; i < 8; i++) a[i] = Ast[(rb + i) * HSA + kk];
                float4 b0 = *(const float4*)&Bft[kk * HSF + cb];
                float4 b1 = *(const float4*)&Bft[kk * HSF + cb + 4];
                float b[8] = {b0.x, b0.y, b0.z, b0.w, b1.x, b1.y, b1.z, b1.w};
                #pragma unroll
                for (int i = 0; i < 8; i++)
                    #pragma unroll
                    for (int j = 0; j < 8; j++)
                        facc[i][j] += a[i] * b[j];
            }

            if (t + 2 < nIter) {
                issue_hyb(As + stw * HASZ, Bt + stw * HBSZ, Bf + stw * HFSZ,
                          A, W, K, Npad, bm0, bn0, (t + 2) * 32, tid);
                stw = (stw == 2) ? 0 : stw + 1;
            }
            st = (st == 2) ? 0 : st + 1;
        }

        const int row0 = bm0 + rb;
        const int col0 = bn0 + 128 + cb;
        #pragma unroll
        for (int i = 0; i < 8; i++) {
            int row = row0 + i;
            #pragma unroll
            for (int j = 0; j < 8; j++) {
                int col = col0 + j;
                if (col < N)
                    C[(size_t)row * N + col] = facc[i][j] + bias[col];
            }
        }
    }
}

// ---------------- flash attention --------------------------------------------
#define QT 64
#define KT 32

__global__ __launch_bounds__(256)
void flash_attn(const float* __restrict__ q,
                const float* __restrict__ k,
                const float* __restrict__ v,
                float* __restrict__ out) {
    const int q0  = blockIdx.x * QT;
    const int h   = blockIdx.y;
    const int b   = blockIdx.z;
    const int tid = threadIdx.x;
    const int qr  = tid >> 2;
    const int qt  = tid & 3;

    __shared__ float Qs[QT][68];
    __shared__ float Ks[KT][68];
    __shared__ float Vs[KT][68];
    __shared__ float Ps[QT][33];

    const size_t base = ((size_t)b * T_) * D_ + (size_t)h * HD_;
    const int qg = q0 + qr;

    #pragma unroll
    for (int i = tid; i < QT * 16; i += 256) {
        int r = i >> 4, c4 = (i & 15) << 2;
        *(float4*)&Qs[r][c4] = *(const float4*)&q[base + (size_t)(q0 + r) * D_ + c4];
    }

    float o[16];
    #pragma unroll
    for (int i = 0; i < 16; i++) o[i] = 0.f;
    float m = -1e30f, l = 0.f;

    const int nTiles = (q0 + QT) / KT;
    __syncthreads();

    for (int t0 = 0; t0 < nTiles; t0++) {
        const int s0 = t0 * KT;
        #pragma unroll
        for (int i = tid; i < KT * 16; i += 256) {
            int r = i >> 4, c4 = (i & 15) << 2;
            *(float4*)&Ks[r][c4] = *(const float4*)&k[base + (size_t)(s0 + r) * D_ + c4];
            *(float4*)&Vs[r][c4] = *(const float4*)&v[base + (size_t)(s0 + r) * D_ + c4];
        }
        __syncthreads();

        float s[8];
        #pragma unroll
        for (int j = 0; j < 8; j++) s[j] = 0.f;
        #pragma unroll
        for (int d4 = 0; d4 < 16; d4++) {
            float4 qv = *(const float4*)&Qs[qr][d4 << 2];
            #pragma unroll
            for (int j = 0; j < 8; j++) {
                float4 kv4 = *(const float4*)&Ks[qt * 8 + j][d4 << 2];
                s[j] += qv.x * kv4.x + qv.y * kv4.y + qv.z * kv4.z + qv.w * kv4.w;
            }
        }
        #pragma unroll
        for (int j = 0; j < 8; j++) {
            int kvg = s0 + qt * 8 + j;
            s[j] = (kvg <= qg) ? s[j] * 0.125f : -1e30f;
        }
        float tm = s[0];
        #pragma unroll
        for (int j = 1; j < 8; j++) tm = fmaxf(tm, s[j]);
        tm = fmaxf(tm, __shfl_xor_sync(0xffffffffu, tm, 1));
        tm = fmaxf(tm, __shfl_xor_sync(0xffffffffu, tm, 2));
        float m_new = fmaxf(m, tm);
        float scale = __expf(m - m_new);
        float ps = 0.f;
        #pragma unroll
        for (int j = 0; j < 8; j++) { s[j] = __expf(s[j] - m_new); ps += s[j]; }
        ps += __shfl_xor_sync(0xffffffffu, ps, 1);
        ps += __shfl_xor_sync(0xffffffffu, ps, 2);
        l = l * scale + ps;
        m = m_new;
        #pragma unroll
        for (int i = 0; i < 16; i++) o[i] *= scale;
        #pragma unroll
        for (int j = 0; j < 8; j++) Ps[qr][qt * 8 + j] = s[j];
        __syncthreads();

        #pragma unroll 4
        for (int kv = 0; kv < KT; kv++) {
            float p = Ps[qr][kv];
            #pragma unroll
            for (int d4 = 0; d4 < 4; d4++) {
                float4 vv = *(const float4*)&Vs[kv][qt * 16 + (d4 << 2)];
                o[d4 * 4 + 0] += p * vv.x;
                o[d4 * 4 + 1] += p * vv.y;
                o[d4 * 4 + 2] += p * vv.z;
                o[d4 * 4 + 3] += p * vv.w;
            }
        }
        __syncthreads();
    }

    float inv = 1.f / l;
    #pragma unroll
    for (int d4 = 0; d4 < 4; d4++) {
        float4 ov = make_float4(f2tf(o[d4 * 4 + 0] * inv), f2tf(o[d4 * 4 + 1] * inv),
                                f2tf(o[d4 * 4 + 2] * inv), f2tf(o[d4 * 4 + 3] * inv));
        *(float4*)&out[base + (size_t)qg * D_ + qt * 16 + (d4 << 2)] = ov;
    }
}

// ---------------- launch -----------------------------------------------------
extern "C" void kernel_launch(void* const* d_in, const int* in_sizes, int n_in,
                              void* d_out, int out_size) {
    const int*   x       = (const int*)  d_in[0];
    const float* tok_emb = (const float*)d_in[1];
    const float* pos_emb = (const float*)d_in[2];
    const float* wq      = (const float*)d_in[3];
    const float* bq      = (const float*)d_in[4];
    const float* wk      = (const float*)d_in[5];
    const float* bk      = (const float*)d_in[6];
    const float* wv      = (const float*)d_in[7];
    const float* bv      = (const float*)d_in[8];
    const float* wo      = (const float*)d_in[9];
    const float* bo      = (const float*)d_in[10];
    const float* ln1_w   = (const float*)d_in[11];
    const float* ln1_b   = (const float*)d_in[12];
    const float* ln2_w   = (const float*)d_in[13];
    const float* ln2_b   = (const float*)d_in[14];
    const float* ffn_w1  = (const float*)d_in[15];
    const float* ffn_b1  = (const float*)d_in[16];
    const float* ffn_w2  = (const float*)d_in[17];
    const float* ffn_b2  = (const float*)d_in[18];
    const float* lnf_w   = (const float*)d_in[19];
    const float* lnf_b   = (const float*)d_in[20];
    const float* proj_w  = (const float*)d_in[21];
    const float* proj_b  = (const float*)d_in[22];
    float* logits = (float*)d_out;

    float *h, *ln, *q, *k, *v, *attn, *mid;
    float *cwq, *cwk, *cwv, *cwo, *cw1, *cw2, *cpj;
    cudaGetSymbolAddress((void**)&h,    g_h);
    cudaGetSymbolAddress((void**)&ln,   g_ln);
    cudaGetSymbolAddress((void**)&q,    g_q);
    cudaGetSymbolAddress((void**)&k,    g_k);
    cudaGetSymbolAddress((void**)&v,    g_v);
    cudaGetSymbolAddress((void**)&attn, g_attn);
    cudaGetSymbolAddress((void**)&mid,  g_mid);
    cudaGetSymbolAddress((void**)&cwq,  g_cwq);
    cudaGetSymbolAddress((void**)&cwk,  g_cwk);
    cudaGetSymbolAddress((void**)&cwv,  g_cwv);
    cudaGetSymbolAddress((void**)&cwo,  g_cwo);
    cudaGetSymbolAddress((void**)&cw1,  g_cw1);
    cudaGetSymbolAddress((void**)&cw2,  g_cw2);
    cudaGetSymbolAddress((void**)&cpj,  g_cpj);

    const int SMEM128 = 3 * (128 * 36 + 32 * 136) * 4;   // 107520 B
    const int SMEM64  = 3 * (128 * 36 + 32 * 72)  * 4;   // 82944 B
    cudaFuncSetAttribute(tgemm<1,128>, cudaFuncAttributeMaxDynamicSharedMemorySize, SMEM128);
    cudaFuncSetAttribute(tgemm<2,64>,  cudaFuncAttributeMaxDynamicSharedMemorySize, SMEM64);
    cudaFuncSetAttribute(tgemm_qkv,    cudaFuncAttributeMaxDynamicSharedMemorySize, SMEM128);
    cudaFuncSetAttribute(tgemm_hyb,    cudaFuncAttributeMaxDynamicSharedMemorySize, SMEM_HYB);

    // ---- weight conversion (tf32 round once per call) ----
    const int sqN4 = L_ * D_ * D_ / 4;
    const int ffN4 = L_ * D_ * FF_ / 4;
    conv_tf32<<<2048, 256>>>((const float4*)wq,     (float4*)cwq, sqN4);
    conv_tf32<<<2048, 256>>>((const float4*)wk,     (float4*)cwk, sqN4);
    conv_tf32<<<2048, 256>>>((const float4*)wv,     (float4*)cwv, sqN4);
    conv_tf32<<<2048, 256>>>((const float4*)wo,     (float4*)cwo, sqN4);
    conv_tf32<<<2048, 256>>>((const float4*)ffn_w1, (float4*)cw1, ffN4);
    conv_tf32<<<2048, 256>>>((const float4*)ffn_w2, (float4*)cw2, ffN4);
    conv_proj<<<4096, 256>>>(proj_w, cpj);

    embed_kernel<<<M_, 256>>>(x, tok_emb, pos_emb, h);

    dim3 gDD64(D_ / 64, M_ / 128);           // (16,16)
    dim3 gQKV(D_ / 128, M_ / 128, 3);        // (8,16,3)
    dim3 gFF1(FF_ / 128, M_ / 128);          // (32,16)
    dim3 gPRJ(VP_ / 192, M_ / 128);          // (262,16)
    dim3 gAT(T_ / QT, H_, B_);

    for (int l = 0; l < L_; l++) {
        float* cwq_l = cwq + (size_t)l * D_ * D_;
        float* cwk_l = cwk + (size_t)l * D_ * D_;
        float* cwv_l = cwv + (size_t)l * D_ * D_;
        float* cwo_l = cwo + (size_t)l * D_ * D_;
        float* cw1_l = cw1 + (size_t)l * D_ * FF_;
        float* cw2_l = cw2 + (size_t)l * FF_ * D_;

        ln_kernel<<<M_, 256>>>(h, ln1_w + l * D_, ln1_b + l * D_, ln);

        tgemm_qkv<<<gQKV, 256, SMEM128>>>(ln, cwq_l, cwk_l, cwv_l,
                                          bq + l * D_, bk + l * D_, bv + l * D_, q, k, v);

        flash_attn<<<gAT, 256>>>(q, k, v, attn);

        tgemm<2,64><<<gDD64, 256, SMEM64>>>(attn, cwo_l, bo + l * D_, h, h, D_, D_, D_);

        ln_kernel<<<M_, 256>>>(h, ln2_w + l * D_, ln2_b + l * D_, ln);

        tgemm<1,128><<<gFF1, 256, SMEM128>>>(ln, cw1_l, ffn_b1 + l * FF_, nullptr, mid,
                                             D_, FF_, FF_);
        tgemm<2,64><<<gDD64, 256, SMEM64>>>(mid, cw2_l, ffn_b2 + l * D_, h, h, FF_, D_, D_);
    }

    ln_kernel<<<M_, 256>>>(h, lnf_w, lnf_b, ln);
    tgemm_hyb<<<gPRJ, 384, SMEM_HYB>>>(ln, cpj, proj_b, logits, D_, V_, VP_);
}

// round 9
// speedup vs baseline: 1.4215x; 1.1215x over previous
#include <cuda_runtime.h>
#include <math.h>

#define B_  2
#define T_  1024
#define D_  1024
#define H_  16
#define HD_ 64
#define FF_ 4096
#define L_  6
#define V_  50257
#define M_  (B_*T_)        // 2048 rows
#define VP_ 50304          // V padded to 128

// ---------------- scratch (static device globals; no allocation) -------------
__device__ float g_h   [M_*D_];
__device__ float g_ln  [M_*D_];
__device__ float g_q   [M_*D_];
__device__ float g_k   [M_*D_];
__device__ float g_v   [M_*D_];
__device__ float g_attn[M_*D_];
__device__ float g_mid [M_*FF_];
// tf32-preconverted weights (row-major [K][N])
__device__ float g_cwq [L_*D_*D_];
__device__ float g_cwk [L_*D_*D_];
__device__ float g_cwv [L_*D_*D_];
__device__ float g_cwo [L_*D_*D_];
__device__ float g_cw1 [L_*D_*FF_];
__device__ float g_cw2 [L_*FF_*D_];
__device__ float g_cpj [(size_t)D_*VP_];

__device__ __forceinline__ float f2tf(float x) {
    unsigned u;
    asm("cvt.rna.tf32.f32 %0, %1;" : "=r"(u) : "f"(x));
    return __uint_as_float(u);
}

// ---------------- weight conversion (fused launches) ---------------------------
__global__ void conv3(const float4* __restrict__ s0, const float4* __restrict__ s1,
                      const float4* __restrict__ s2,
                      float4* __restrict__ d0, float4* __restrict__ d1,
                      float4* __restrict__ d2,
                      int n0, int n1, int n2) {
    const float4* s = (blockIdx.y == 0) ? s0 : (blockIdx.y == 1) ? s1 : s2;
    float4*       d = (blockIdx.y == 0) ? d0 : (blockIdx.y == 1) ? d1 : d2;
    int n4          = (blockIdx.y == 0) ? n0 : (blockIdx.y == 1) ? n1 : n2;
    for (int i = blockIdx.x * blockDim.x + threadIdx.x; i < n4; i += gridDim.x * blockDim.x) {
        float4 v = s[i];
        d[i] = make_float4(f2tf(v.x), f2tf(v.y), f2tf(v.z), f2tf(v.w));
    }
}

__global__ void conv_proj(const float* __restrict__ src, float* __restrict__ dst) {
    const long long total = (long long)D_ * VP_;
    for (long long i = (long long)blockIdx.x * blockDim.x + threadIdx.x; i < total;
         i += (long long)gridDim.x * blockDim.x) {
        int row = (int)(i / VP_), col = (int)(i - (long long)row * VP_);
        dst[i] = (col < V_) ? f2tf(src[(size_t)row * V_ + col]) : 0.f;
    }
}

// ---------------- embedding --------------------------------------------------
__global__ void embed_kernel(const int* __restrict__ x,
                             const float* __restrict__ tok,
                             const float* __restrict__ pos,
                             float* __restrict__ h) {
    int row = blockIdx.x;
    int t   = row % T_;
    int id  = x[row];
    const float* te = tok + (size_t)id * D_;
    const float* pe = pos + (size_t)t  * D_;
    float* o = h + (size_t)row * D_;
    for (int d = threadIdx.x; d < D_; d += blockDim.x)
        o[d] = te[d] + pe[d];
}

// ---------------- layernorm (tf32-rounded output) ----------------------------
__global__ void ln_kernel(const float* __restrict__ in,
                          const float* __restrict__ w,
                          const float* __restrict__ b,
                          float* __restrict__ out) {
    int row = blockIdx.x;
    int tid = threadIdx.x;
    const float* xr = in + (size_t)row * D_;
    float s = 0.f, sq = 0.f;
    for (int d = tid; d < D_; d += 256) {
        float v = xr[d];
        s  += v;
        sq += v * v;
    }
    __shared__ float rs[256], rq[256];
    rs[tid] = s; rq[tid] = sq;
    __syncthreads();
    for (int off = 128; off > 0; off >>= 1) {
        if (tid < off) { rs[tid] += rs[tid + off]; rq[tid] += rq[tid + off]; }
        __syncthreads();
    }
    float mu  = rs[0] * (1.f / D_);
    float var = rq[0] * (1.f / D_) - mu * mu;
    float inv = rsqrtf(var + 1e-5f);
    float* o = out + (size_t)row * D_;
    for (int d = tid; d < D_; d += 256)
        o[d] = f2tf((xr[d] - mu) * inv * w[d] + b[d]);
}

// ---------------- common GEMM helpers ------------------------------------------
#define CPA16(dst_u32, src_ptr) \
    asm volatile("cp.async.cg.shared.global [%0], [%1], 16;" :: "r"(dst_u32), "l"(src_ptr))

__device__ __forceinline__ unsigned smem_u32(const void* p) {
    return (unsigned)__cvta_generic_to_shared(p);
}

__device__ __forceinline__ void mma8(float c[4], const unsigned a[4], const unsigned b[2]) {
    asm volatile(
        "mma.sync.aligned.m16n8k8.row.col.f32.tf32.tf32.f32 "
        "{%0,%1,%2,%3}, {%4,%5,%6,%7}, {%8,%9}, {%0,%1,%2,%3};\n"
        : "+f"(c[0]), "+f"(c[1]), "+f"(c[2]), "+f"(c[3])
        : "r"(a[0]), "r"(a[1]), "r"(a[2]), "r"(a[3]), "r"(b[0]), "r"(b[1]));
}

// ---------------- standard GEMM: 128 x BN_, 3-stage cp.async (R4 proven) ------
// MODE 0: +bias   MODE 1: f2tf(relu(+bias))   MODE 2: +bias + residual R
// GUARD 1: col<N guard on bias read + store (vocab tail)
template <int BN_>
__device__ __forceinline__ void issue_stage(
    float* As, float* Bs, const float* A, const float* W,
    int K, int Npad, int bm0, int bn0, int k0, int tid)
{
    constexpr int SB = BN_ + 8;
    #pragma unroll
    for (int j = 0; j < 4; j++) {
        int f = tid + j * 256;
        int row = f >> 3, c4 = (f & 7) << 2;
        CPA16(smem_u32(As + row * 36 + c4), A + (size_t)(bm0 + row) * K + k0 + c4);
    }
    #pragma unroll
    for (int j = 0; j < BN_ / 32; j++) {
        int f = tid + j * 256;
        int row = (BN_ == 128) ? (f >> 5) : (f >> 4);
        int c4  = (BN_ == 128) ? ((f & 31) << 2) : ((f & 15) << 2);
        CPA16(smem_u32(Bs + row * SB + c4), W + (size_t)(k0 + row) * Npad + bn0 + c4);
    }
    asm volatile("cp.async.commit_group;");
}

template <int MODE, int BN_, int GUARD>
__device__ __forceinline__ void tgemm_body(
    const float* __restrict__ A, const float* __restrict__ W,
    const float* __restrict__ bias, const float* __restrict__ R,
    float* __restrict__ C, int K, int N, int Npad, int bm0, int bn0)
{
    constexpr int SB  = BN_ + 8;
    constexpr int ASZ = 128 * 36;
    constexpr int BSZ = 32 * SB;
    constexpr int NI  = BN_ / 32;

    extern __shared__ float sm[];
    float* As = sm;
    float* Bs = sm + 3 * ASZ;

    const int tid  = threadIdx.x;
    const int lane = tid & 31;
    const int warp = tid >> 5;
    const int g    = lane >> 2;
    const int tg   = lane & 3;
    const int wm0  = (warp >> 2) * 64;
    const int wn0  = (warp & 3) * (BN_ / 4);

    float acc[4][NI][4];
    #pragma unroll
    for (int mi = 0; mi < 4; mi++)
        #pragma unroll
        for (int ni = 0; ni < NI; ni++)
            #pragma unroll
            for (int r = 0; r < 4; r++) acc[mi][ni][r] = 0.f;

    const int nIter = K / 32;
    issue_stage<BN_>(As, Bs, A, W, K, Npad, bm0, bn0, 0, tid);
    issue_stage<BN_>(As + ASZ, Bs + BSZ, A, W, K, Npad, bm0, bn0, 32, tid);

    int st = 0, stw = 2;
    for (int t = 0; t < nIter; t++) {
        if (t + 1 < nIter) asm volatile("cp.async.wait_group 1;");
        else               asm volatile("cp.async.wait_group 0;");
        __syncthreads();

        const float* Ast = As + st * ASZ;
        const float* Bst = Bs + st * BSZ;
        #pragma unroll
        for (int kk = 0; kk < 32; kk += 8) {
            unsigned a[4][4], b[NI][2];
            #pragma unroll
            for (int mi = 0; mi < 4; mi++) {
                int r0 = wm0 + mi * 16 + g;
                a[mi][0] = __float_as_uint(Ast[(r0    ) * 36 + kk + tg]);
                a[mi][1] = __float_as_uint(Ast[(r0 + 8) * 36 + kk + tg]);
                a[mi][2] = __float_as_uint(Ast[(r0    ) * 36 + kk + tg + 4]);
                a[mi][3] = __float_as_uint(Ast[(r0 + 8) * 36 + kk + tg + 4]);
            }
            #pragma unroll
            for (int ni = 0; ni < NI; ni++) {
                int c = wn0 + ni * 8 + g;
                b[ni][0] = __float_as_uint(Bst[(kk + tg    ) * SB + c]);
                b[ni][1] = __float_as_uint(Bst[(kk + tg + 4) * SB + c]);
            }
            #pragma unroll
            for (int mi = 0; mi < 4; mi++)
                #pragma unroll
                for (int ni = 0; ni < NI; ni++)
                    mma8(acc[mi][ni], a[mi], b[ni]);
        }

        if (t + 2 < nIter) {
            issue_stage<BN_>(As + stw * ASZ, Bs + stw * BSZ, A, W, K, Npad, bm0, bn0,
                             (t + 2) * 32, tid);
            stw = (stw == 2) ? 0 : stw + 1;
        }
        st = (st == 2) ? 0 : st + 1;
    }

    #pragma unroll
    for (int mi = 0; mi < 4; mi++) {
        #pragma unroll
        for (int ni = 0; ni < NI; ni++) {
            int row0 = bm0 + wm0 + mi * 16 + g;
            int col0 = bn0 + wn0 + ni * 8 + 2 * tg;
            #pragma unroll
            for (int rr = 0; rr < 2; rr++) {
                int row = row0 + rr * 8;
                #pragma unroll
                for (int cc = 0; cc < 2; cc++) {
                    int col = col0 + cc;
                    if (!GUARD || col < N) {
                        float v = acc[mi][ni][rr * 2 + cc] + bias[col];
                        if (MODE == 1) v = f2tf(fmaxf(v, 0.f));
                        if (MODE == 2) v += R[(size_t)row * N + col];
                        C[(size_t)row * N + col] = v;
                    }
                }
            }
        }
    }
}

// bn-fastest grid (default; A-tile reuse across the wave)
template <int MODE, int BN_, int GUARD>
__global__ __launch_bounds__(256, 2)
void tgemm(const float* __restrict__ A, const float* __restrict__ W,
           const float* __restrict__ bias, const float* __restrict__ R,
           float* __restrict__ C, int K, int N, int Npad) {
    tgemm_body<MODE, BN_, GUARD>(A, W, bias, R, C, K, N, Npad,
                                 blockIdx.y * 128, blockIdx.x * BN_);
}

// bm-fastest grid (B-tile reuse across the wave; for N >> M GEMMs)
template <int MODE, int BN_, int GUARD>
__global__ __launch_bounds__(256, 2)
void tgemm_s(const float* __restrict__ A, const float* __restrict__ W,
             const float* __restrict__ bias, const float* __restrict__ R,
             float* __restrict__ C, int K, int N, int Npad) {
    tgemm_body<MODE, BN_, GUARD>(A, W, bias, R, C, K, N, Npad,
                                 blockIdx.x * 128, blockIdx.y * BN_);
}

__global__ __launch_bounds__(256, 2)
void tgemm_qkv(const float* __restrict__ A,
               const float* __restrict__ wq, const float* __restrict__ wk,
               const float* __restrict__ wv,
               const float* __restrict__ bq, const float* __restrict__ bk,
               const float* __restrict__ bv,
               float* __restrict__ q, float* __restrict__ k, float* __restrict__ v) {
    int z = blockIdx.z;
    const float* W    = (z == 0) ? wq : (z == 1) ? wk : wv;
    const float* bias = (z == 0) ? bq : (z == 1) ? bk : bv;
    float*       C    = (z == 0) ? q  : (z == 1) ? k  : v;
    tgemm_body<0, 128, 0>(A, W, bias, nullptr, C, D_, D_, D_,
                          blockIdx.y * 128, blockIdx.x * 128);
}

// ---------------- flash attention --------------------------------------------
#define QT 64
#define KT 32

__global__ __launch_bounds__(256)
void flash_attn(const float* __restrict__ q,
                const float* __restrict__ k,
                const float* __restrict__ v,
                float* __restrict__ out) {
    const int q0  = blockIdx.x * QT;
    const int h   = blockIdx.y;
    const int b   = blockIdx.z;
    const int tid = threadIdx.x;
    const int qr  = tid >> 2;
    const int qt  = tid & 3;

    __shared__ float Qs[QT][68];
    __shared__ float Ks[KT][68];
    __shared__ float Vs[KT][68];
    __shared__ float Ps[QT][33];

    const size_t base = ((size_t)b * T_) * D_ + (size_t)h * HD_;
    const int qg = q0 + qr;

    #pragma unroll
    for (int i = tid; i < QT * 16; i += 256) {
        int r = i >> 4, c4 = (i & 15) << 2;
        *(float4*)&Qs[r][c4] = *(const float4*)&q[base + (size_t)(q0 + r) * D_ + c4];
    }

    float o[16];
    #pragma unroll
    for (int i = 0; i < 16; i++) o[i] = 0.f;
    float m = -1e30f, l = 0.f;

    const int nTiles = (q0 + QT) / KT;
    __syncthreads();

    for (int t0 = 0; t0 < nTiles; t0++) {
        const int s0 = t0 * KT;
        #pragma unroll
        for (int i = tid; i < KT * 16; i += 256) {
            int r = i >> 4, c4 = (i & 15) << 2;
            *(float4*)&Ks[r][c4] = *(const float4*)&k[base + (size_t)(s0 + r) * D_ + c4];
            *(float4*)&Vs[r][c4] = *(const float4*)&v[base + (size_t)(s0 + r) * D_ + c4];
        }
        __syncthreads();

        float s[8];
        #pragma unroll
        for (int j = 0; j < 8; j++) s[j] = 0.f;
        #pragma unroll
        for (int d4 = 0; d4 < 16; d4++) {
            float4 qv = *(const float4*)&Qs[qr][d4 << 2];
            #pragma unroll
            for (int j = 0; j < 8; j++) {
                float4 kv4 = *(const float4*)&Ks[qt * 8 + j][d4 << 2];
                s[j] += qv.x * kv4.x + qv.y * kv4.y + qv.z * kv4.z + qv.w * kv4.w;
            }
        }
        #pragma unroll
        for (int j = 0; j < 8; j++) {
            int kvg = s0 + qt * 8 + j;
            s[j] = (kvg <= qg) ? s[j] * 0.125f : -1e30f;
        }
        float tm = s[0];
        #pragma unroll
        for (int j = 1; j < 8; j++) tm = fmaxf(tm, s[j]);
        tm = fmaxf(tm, __shfl_xor_sync(0xffffffffu, tm, 1));
        tm = fmaxf(tm, __shfl_xor_sync(0xffffffffu, tm, 2));
        float m_new = fmaxf(m, tm);
        float scale = __expf(m - m_new);
        float ps = 0.f;
        #pragma unroll
        for (int j = 0; j < 8; j++) { s[j] = __expf(s[j] - m_new); ps += s[j]; }
        ps += __shfl_xor_sync(0xffffffffu, ps, 1);
        ps += __shfl_xor_sync(0xffffffffu, ps, 2);
        l = l * scale + ps;
        m = m_new;
        #pragma unroll
        for (int i = 0; i < 16; i++) o[i] *= scale;
        #pragma unroll
        for (int j = 0; j < 8; j++) Ps[qr][qt * 8 + j] = s[j];
        __syncthreads();

        #pragma unroll 4
        for (int kv = 0; kv < KT; kv++) {
            float p = Ps[qr][kv];
            #pragma unroll
            for (int d4 = 0; d4 < 4; d4++) {
                float4 vv = *(const float4*)&Vs[kv][qt * 16 + (d4 << 2)];
                o[d4 * 4 + 0] += p * vv.x;
                o[d4 * 4 + 1] += p * vv.y;
                o[d4 * 4 + 2] += p * vv.z;
                o[d4 * 4 + 3] += p * vv.w;
            }
        }
        __syncthreads();
    }

    float inv = 1.f / l;
    #pragma unroll
    for (int d4 = 0; d4 < 4; d4++) {
        float4 ov = make_float4(f2tf(o[d4 * 4 + 0] * inv), f2tf(o[d4 * 4 + 1] * inv),
                                f2tf(o[d4 * 4 + 2] * inv), f2tf(o[d4 * 4 + 3] * inv));
        *(float4*)&out[base + (size_t)qg * D_ + qt * 16 + (d4 << 2)] = ov;
    }
}

// ---------------- launch -----------------------------------------------------
extern "C" void kernel_launch(void* const* d_in, const int* in_sizes, int n_in,
                              void* d_out, int out_size) {
    const int*   x       = (const int*)  d_in[0];
    const float* tok_emb = (const float*)d_in[1];
    const float* pos_emb = (const float*)d_in[2];
    const float* wq      = (const float*)d_in[3];
    const float* bq      = (const float*)d_in[4];
    const float* wk      = (const float*)d_in[5];
    const float* bk      = (const float*)d_in[6];
    const float* wv      = (const float*)d_in[7];
    const float* bv      = (const float*)d_in[8];
    const float* wo      = (const float*)d_in[9];
    const float* bo      = (const float*)d_in[10];
    const float* ln1_w   = (const float*)d_in[11];
    const float* ln1_b   = (const float*)d_in[12];
    const float* ln2_w   = (const float*)d_in[13];
    const float* ln2_b   = (const float*)d_in[14];
    const float* ffn_w1  = (const float*)d_in[15];
    const float* ffn_b1  = (const float*)d_in[16];
    const float* ffn_w2  = (const float*)d_in[17];
    const float* ffn_b2  = (const float*)d_in[18];
    const float* lnf_w   = (const float*)d_in[19];
    const float* lnf_b   = (const float*)d_in[20];
    const float* proj_w  = (const float*)d_in[21];
    const float* proj_b  = (const float*)d_in[22];
    float* logits = (float*)d_out;

    float *h, *ln, *q, *k, *v, *attn, *mid;
    float *cwq, *cwk, *cwv, *cwo, *cw1, *cw2, *cpj;
    cudaGetSymbolAddress((void**)&h,    g_h);
    cudaGetSymbolAddress((void**)&ln,   g_ln);
    cudaGetSymbolAddress((void**)&q,    g_q);
    cudaGetSymbolAddress((void**)&k,    g_k);
    cudaGetSymbolAddress((void**)&v,    g_v);
    cudaGetSymbolAddress((void**)&attn, g_attn);
    cudaGetSymbolAddress((void**)&mid,  g_mid);
    cudaGetSymbolAddress((void**)&cwq,  g_cwq);
    cudaGetSymbolAddress((void**)&cwk,  g_cwk);
    cudaGetSymbolAddress((void**)&cwv,  g_cwv);
    cudaGetSymbolAddress((void**)&cwo,  g_cwo);
    cudaGetSymbolAddress((void**)&cw1,  g_cw1);
    cudaGetSymbolAddress((void**)&cw2,  g_cw2);
    cudaGetSymbolAddress((void**)&cpj,  g_cpj);

    const int SMEM128 = 3 * (128 * 36 + 32 * 136) * 4;   // 107520 B
    const int SMEM64  = 3 * (128 * 36 + 32 * 72)  * 4;   // 82944 B
    cudaFuncSetAttribute(tgemm<2,64,0>,   cudaFuncAttributeMaxDynamicSharedMemorySize, SMEM64);
    cudaFuncSetAttribute(tgemm_s<1,128,0>,cudaFuncAttributeMaxDynamicSharedMemorySize, SMEM128);
    cudaFuncSetAttribute(tgemm_s<0,128,1>,cudaFuncAttributeMaxDynamicSharedMemorySize, SMEM128);
    cudaFuncSetAttribute(tgemm_qkv,       cudaFuncAttributeMaxDynamicSharedMemorySize, SMEM128);

    const int sqN4 = L_ * D_ * D_ / 4;
    const int ffN4 = L_ * D_ * FF_ / 4;

    // Launch order chosen so launch #6 (ncu -s 5 -c 1) is tgemm_qkv.
    embed_kernel<<<M_, 256>>>(x, tok_emb, pos_emb, h);                       // 1
    conv3<<<dim3(1024, 3), 256>>>((const float4*)wq, (const float4*)wk,
                                  (const float4*)wv,
                                  (float4*)cwq, (float4*)cwk, (float4*)cwv,
                                  sqN4, sqN4, sqN4);                         // 2
    conv3<<<dim3(2048, 3), 256>>>((const float4*)wo, (const float4*)ffn_w1,
                                  (const float4*)ffn_w2,
                                  (float4*)cwo, (float4*)cw1, (float4*)cw2,
                                  sqN4, ffN4, ffN4);                         // 3
    conv_proj<<<4096, 256>>>(proj_w, cpj);                                   // 4

    dim3 gDD64(D_ / 64, M_ / 128);           // (16,16)  bn-fastest
    dim3 gQKV(D_ / 128, M_ / 128, 3);        // (8,16,3)
    dim3 gFF1(M_ / 128, FF_ / 128);          // (16,32)  bm-fastest
    dim3 gPRJ(M_ / 128, VP_ / 128);          // (16,393) bm-fastest
    dim3 gAT(T_ / QT, H_, B_);

    for (int l = 0; l < L_; l++) {
        float* cwq_l = cwq + (size_t)l * D_ * D_;
        float* cwk_l = cwk + (size_t)l * D_ * D_;
        float* cwv_l = cwv + (size_t)l * D_ * D_;
        float* cwo_l = cwo + (size_t)l * D_ * D_;
        float* cw1_l = cw1 + (size_t)l * D_ * FF_;
        float* cw2_l = cw2 + (size_t)l * FF_ * D_;

        ln_kernel<<<M_, 256>>>(h, ln1_w + l * D_, ln1_b + l * D_, ln);       // 5 (l=0)

        tgemm_qkv<<<gQKV, 256, SMEM128>>>(ln, cwq_l, cwk_l, cwv_l,
                                          bq + l * D_, bk + l * D_, bv + l * D_,
                                          q, k, v);                          // 6 (l=0) <- profiled

        flash_attn<<<gAT, 256>>>(q, k, v, attn);

        tgemm<2,64,0><<<gDD64, 256, SMEM64>>>(attn, cwo_l, bo + l * D_, h, h,
                                              D_, D_, D_);

        ln_kernel<<<M_, 256>>>(h, ln2_w + l * D_, ln2_b + l * D_, ln);

        tgemm_s<1,128,0><<<gFF1, 256, SMEM128>>>(ln, cw1_l, ffn_b1 + l * FF_,
                                                 nullptr, mid, D_, FF_, FF_);
        tgemm<2,64,0><<<gDD64, 256, SMEM64>>>(mid, cw2_l, ffn_b2 + l * D_, h, h,
                                              FF_, D_, D_);
    }

    ln_kernel<<<M_, 256>>>(h, lnf_w, lnf_b, ln);
    tgemm_s<0,128,1><<<gPRJ, 256, SMEM128>>>(ln, cpj, proj_b, nullptr, logits,
                                             D_, V_, VP_);
}